// round 11
// baseline (speedup 1.0000x reference)
#include <cuda_runtime.h>
#include <cuda_bf16.h>
#include <cstdint>

// ---------------- scratch (no mallocs allowed) ----------------
__device__ __align__(16) float g_xt[784 * 4096];        // x^T  (pixel, n)
__device__ __align__(16) float g_h1[16 * 169 * 4096];   // layer1 pooled (c,13,13, n)
__device__ __align__(16) float g_h2[800 * 4096];        // layer2 pooled (feature, n)
__device__ __align__(16) float g_h3p[8][128 * 4096];    // fc1 split-K partial sums

// ---------------- f32x2 helpers (FFMA2 path: 2 MACs/instr) ----------------
static __device__ __forceinline__ unsigned long long ffma2(unsigned long long a,
                                                           unsigned long long b,
                                                           unsigned long long c) {
    unsigned long long d;
    asm("fma.rn.f32x2 %0, %1, %2, %3;" : "=l"(d) : "l"(a), "l"(b), "l"(c));
    return d;
}
static __device__ __forceinline__ unsigned long long pack2(float lo, float hi) {
    unsigned long long r;
    asm("mov.b64 %0, {%1, %2};" : "=l"(r) : "f"(lo), "f"(hi));
    return r;
}
static __device__ __forceinline__ float2 unpk(unsigned long long v) {
    float2 r;
    asm("mov.b64 {%0, %1}, %2;" : "=f"(r.x), "=f"(r.y) : "l"(v));
    return r;
}

// ---------------- K0: transpose x (4096,784) -> (784,4096) ----------------
__global__ __launch_bounds__(256) void k_transpose(const float* __restrict__ x) {
    __shared__ float tile[32][33];
    int p0 = blockIdx.x * 32;
    int n0 = blockIdx.y * 32;
    int tx = threadIdx.x, ty = threadIdx.y;   // (32,8)
#pragma unroll
    for (int i = 0; i < 4; i++) {
        int n = n0 + ty + i * 8, p = p0 + tx;
        float v = 0.f;
        if (p < 784) v = x[n * 784 + p];
        tile[ty + i * 8][tx] = v;
    }
    __syncthreads();
#pragma unroll
    for (int i = 0; i < 4; i++) {
        int p = p0 + ty + i * 8, n = n0 + tx;
        if (p < 784) g_xt[p * 4096 + n] = tile[tx][ty + i * 8];
    }
}

// ---------------- K1: layer1 lc-conv + relu + maxpool2 ----------------
// grid (169, 4), block 256. Each CTA: one pooled position, all 16 out channels,
// 1024 batch elems (4 per thread as 2x f32x2).
__global__ __launch_bounds__(256) void k_layer1(const float* __restrict__ w1,
                                                const float* __restrict__ b1) {
    int pos = blockIdx.x;                 // 0..168
    int pi = pos / 13, pj = pos % 13;
    int tid = threadIdx.x;
    __shared__ unsigned long long swd[16 * 36];   // [o][p][k], value duplicated
    __shared__ unsigned long long sbd[16 * 4];    // [o][p] bias duplicated

    for (int idx = tid; idx < 576; idx += 256) {
        int k = idx % 9, t = idx / 9;
        int p = t & 3, o = t >> 2;
        int ci = 2 * pi + (p >> 1), cj = 2 * pj + (p & 1);
        float w = w1[((o * 9 + k) * 26 + ci) * 26 + cj];
        swd[(o * 4 + p) * 9 + k] = pack2(w, w);
    }
    if (tid < 64) {
        int p = tid & 3, o = tid >> 2;
        int ci = 2 * pi + (p >> 1), cj = 2 * pj + (p & 1);
        float bb = b1[(o * 26 + ci) * 26 + cj];
        sbd[tid] = pack2(bb, bb);
    }
    __syncthreads();

    int n = (blockIdx.y * 256 + tid) * 4;

    unsigned long long xv[32];            // 4x4 region, 4 n-lanes (2 u64 each)
#pragma unroll
    for (int r = 0; r < 4; r++)
#pragma unroll
        for (int c = 0; c < 4; c++) {
            ulonglong2 v = *(const ulonglong2*)&g_xt[((2 * pi + r) * 28 + (2 * pj + c)) * 4096 + n];
            xv[(r * 4 + c) * 2 + 0] = v.x;
            xv[(r * 4 + c) * 2 + 1] = v.y;
        }

#pragma unroll 1
    for (int o = 0; o < 16; o++) {
        unsigned long long a[4][2];
#pragma unroll
        for (int p = 0; p < 4; p++) { a[p][0] = sbd[o * 4 + p]; a[p][1] = sbd[o * 4 + p]; }
#pragma unroll
        for (int p = 0; p < 4; p++) {
            int di = p >> 1, dj = p & 1;
#pragma unroll
            for (int k = 0; k < 9; k++) {
                unsigned long long w = swd[(o * 4 + p) * 9 + k];
                int xi = (di + k / 3) * 4 + (dj + k % 3);
                a[p][0] = ffma2(w, xv[xi * 2 + 0], a[p][0]);
                a[p][1] = ffma2(w, xv[xi * 2 + 1], a[p][1]);
            }
        }
        float2 a0 = unpk(a[0][0]), a1 = unpk(a[1][0]), a2 = unpk(a[2][0]), a3 = unpk(a[3][0]);
        float2 b0 = unpk(a[0][1]), bq = unpk(a[1][1]), b2_ = unpk(a[2][1]), b3 = unpk(a[3][1]);
        float4 r;
        r.x = fmaxf(fmaxf(fmaxf(a0.x, a1.x), fmaxf(a2.x, a3.x)), 0.f);
        r.y = fmaxf(fmaxf(fmaxf(a0.y, a1.y), fmaxf(a2.y, a3.y)), 0.f);
        r.z = fmaxf(fmaxf(fmaxf(b0.x, bq.x), fmaxf(b2_.x, b3.x)), 0.f);
        r.w = fmaxf(fmaxf(fmaxf(b0.y, bq.y), fmaxf(b2_.y, b3.y)), 0.f);
        *(float4*)&g_h1[(o * 169 + pos) * 4096 + n] = r;
    }
}

// ---------------- K2: layer2 lc-conv + relu + maxpool2 ----------------
// grid (25, 4, 8), block 256. CTA: one pooled position, 8 out channels,
// 512 batch elems (2 per thread = 1 f32x2).
__global__ __launch_bounds__(256) void k_layer2(const float* __restrict__ w2,
                                                const float* __restrict__ b2) {
    int pos = blockIdx.x;                 // 0..24
    int pi = pos / 5, pj = pos % 5;
    int o0 = blockIdx.y * 8;
    int tid = threadIdx.x;
    __shared__ unsigned long long swd[8 * 576];   // [((o*16+c)*9+k)*4+p]
    __shared__ unsigned long long sbd[8 * 4];

    for (int idx = tid; idx < 8 * 576; idx += 256) {
        int p = idx & 3;
        int t = idx >> 2;
        int k = t % 9;
        int u = t / 9;
        int c = u & 15, o = u >> 4;
        int ci = 2 * pi + (p >> 1), cj = 2 * pj + (p & 1);
        float w = w2[((((o0 + o) * 16 + c) * 9 + k) * 11 + ci) * 11 + cj];
        swd[idx] = pack2(w, w);
    }
    if (tid < 32) {
        int p = tid & 3, o = tid >> 2;
        int ci = 2 * pi + (p >> 1), cj = 2 * pj + (p & 1);
        float bb = b2[((o0 + o) * 11 + ci) * 11 + cj];
        sbd[tid] = pack2(bb, bb);
    }
    __syncthreads();

    int n = blockIdx.z * 512 + tid * 2;

    unsigned long long acc[8][4];
#pragma unroll
    for (int o = 0; o < 8; o++)
#pragma unroll
        for (int p = 0; p < 4; p++) acc[o][p] = sbd[o * 4 + p];

#pragma unroll 1
    for (int c = 0; c < 16; c++) {
        unsigned long long hv[16];
#pragma unroll
        for (int r = 0; r < 4; r++)
#pragma unroll
            for (int cc = 0; cc < 4; cc++)
                hv[r * 4 + cc] =
                    *(const unsigned long long*)&g_h1[((c * 169) + (2 * pi + r) * 13 + (2 * pj + cc)) * 4096 + n];
#pragma unroll
        for (int o = 0; o < 8; o++) {
#pragma unroll
            for (int p = 0; p < 4; p++) {
                int di = p >> 1, dj = p & 1;
#pragma unroll
                for (int k = 0; k < 9; k++) {
                    acc[o][p] = ffma2(swd[((o * 16 + c) * 9 + k) * 4 + p],
                                      hv[(di + k / 3) * 4 + (dj + k % 3)], acc[o][p]);
                }
            }
        }
    }

#pragma unroll
    for (int o = 0; o < 8; o++) {
        float2 a0 = unpk(acc[o][0]), a1 = unpk(acc[o][1]);
        float2 a2 = unpk(acc[o][2]), a3 = unpk(acc[o][3]);
        float2 r;
        r.x = fmaxf(fmaxf(fmaxf(a0.x, a1.x), fmaxf(a2.x, a3.x)), 0.f);
        r.y = fmaxf(fmaxf(fmaxf(a0.y, a1.y), fmaxf(a2.y, a3.y)), 0.f);
        *(float2*)&g_h2[((o0 + o) * 25 + pos) * 4096 + n] = r;
    }
}

// ---------------- K3: fc1 (800 -> 128), split-K=8, partial sums ----------------
// grid (16 n-tiles, 4 j-tiles, 8 splits of 100 ff), block 256 = 32 n x 8 j-groups.
// Thread tile: 8 n x 4 j (2x LDG.128 + 16 FFMA2 per ff). Explicit h prefetch
// double-buffer forces >=2 iterations of loads in flight. Bias+ReLU in k_fc2.
__global__ __launch_bounds__(256) void k_fc1(const float* __restrict__ w) {
    __shared__ unsigned long long wsd[100 * 32];   // [ff][jj] duplicated, 25.6KB
    int tid = threadIdx.x;
    int nt = tid & 31, jg = tid >> 5;              // warp-uniform jg -> LDS broadcast
    int n  = blockIdx.x * 256 + nt * 8;
    int jb = blockIdx.y * 32;
    int f0 = blockIdx.z * 100;

    for (int i = tid; i < 3200; i += 256) {
        int ff = i >> 5, jj = i & 31;
        float wv = w[(f0 + ff) * 128 + jb + jj];
        wsd[i] = pack2(wv, wv);
    }
    __syncthreads();

    unsigned long long acc[4][4];
#pragma unroll
    for (int jj = 0; jj < 4; jj++)
#pragma unroll
        for (int q = 0; q < 4; q++) acc[jj][q] = 0ULL;

    // prefetch iteration 0
    ulonglong2 h0 = *(const ulonglong2*)&g_h2[f0 * 4096 + n];
    ulonglong2 h1 = *(const ulonglong2*)&g_h2[f0 * 4096 + n + 4];

#pragma unroll 4
    for (int ff = 0; ff < 100; ff++) {
        ulonglong2 c0 = h0, c1 = h1;
        if (ff < 99) {
            h0 = *(const ulonglong2*)&g_h2[(f0 + ff + 1) * 4096 + n];
            h1 = *(const ulonglong2*)&g_h2[(f0 + ff + 1) * 4096 + n + 4];
        }
#pragma unroll
        for (int jj = 0; jj < 4; jj++) {
            unsigned long long wv = wsd[ff * 32 + jg * 4 + jj];
            acc[jj][0] = ffma2(wv, c0.x, acc[jj][0]);
            acc[jj][1] = ffma2(wv, c0.y, acc[jj][1]);
            acc[jj][2] = ffma2(wv, c1.x, acc[jj][2]);
            acc[jj][3] = ffma2(wv, c1.y, acc[jj][3]);
        }
    }

#pragma unroll
    for (int jj = 0; jj < 4; jj++) {
        int j = jb + jg * 4 + jj;
        ulonglong2 v0, v1;
        v0.x = acc[jj][0]; v0.y = acc[jj][1];
        v1.x = acc[jj][2]; v1.y = acc[jj][3];
        *(ulonglong2*)&g_h3p[blockIdx.z][j * 4096 + n]     = v0;
        *(ulonglong2*)&g_h3p[blockIdx.z][j * 4096 + n + 4] = v1;
    }
}

// ---------------- K4: fc2 (128 -> 10), with split-K reduce + bias + relu ----------------
__global__ __launch_bounds__(256) void k_fc2(const float* __restrict__ w,
                                             const float* __restrict__ b,
                                             const float* __restrict__ fc1b,
                                             float* __restrict__ out) {
    __shared__ float ws[1280];
    __shared__ float bs[10];
    __shared__ float b1s[128];
    int tid = threadIdx.x;
    for (int i = tid; i < 1280; i += 256) ws[i] = w[i];
    if (tid < 10) bs[tid] = b[tid];
    if (tid < 128) b1s[tid] = fc1b[tid];
    __syncthreads();

    int n = blockIdx.x * 256 + tid;
    float acc[10];
#pragma unroll
    for (int j = 0; j < 10; j++) acc[j] = bs[j];
#pragma unroll 4
    for (int f = 0; f < 128; f++) {
        float h = ((g_h3p[0][f * 4096 + n] + g_h3p[1][f * 4096 + n]) +
                   (g_h3p[2][f * 4096 + n] + g_h3p[3][f * 4096 + n])) +
                  ((g_h3p[4][f * 4096 + n] + g_h3p[5][f * 4096 + n]) +
                   (g_h3p[6][f * 4096 + n] + g_h3p[7][f * 4096 + n]));
        h = fmaxf(h + b1s[f], 0.f);
#pragma unroll
        for (int j = 0; j < 10; j++) acc[j] = fmaf(ws[f * 10 + j], h, acc[j]);
    }
#pragma unroll
    for (int j = 0; j < 10; j++) out[n * 10 + j] = acc[j];
}

// ---------------- launch ----------------
extern "C" void kernel_launch(void* const* d_in, const int* in_sizes, int n_in,
                              void* d_out, int out_size) {
    const float* x    = (const float*)d_in[0];
    const float* w1   = (const float*)d_in[1];
    const float* b1   = (const float*)d_in[2];
    const float* w2   = (const float*)d_in[3];
    const float* b2   = (const float*)d_in[4];
    const float* fc1w = (const float*)d_in[5];
    const float* fc1b = (const float*)d_in[6];
    const float* fc2w = (const float*)d_in[7];
    const float* fc2b = (const float*)d_in[8];
    float* out = (float*)d_out;

    k_transpose<<<dim3(25, 128), dim3(32, 8)>>>(x);
    k_layer1<<<dim3(169, 4), 256>>>(w1, b1);
    k_layer2<<<dim3(25, 4, 8), 256>>>(w2, b2);
    k_fc1<<<dim3(16, 4, 8), 256>>>(fc1w);
    k_fc2<<<16, 256>>>(fc2w, fc2b, fc1b, out);
}

// round 13
// speedup vs baseline: 1.0522x; 1.0522x over previous
#include <cuda_runtime.h>
#include <cuda_bf16.h>
#include <cstdint>

// ---------------- scratch (no mallocs allowed) ----------------
__device__ __align__(16) float g_xt[784 * 4096];        // x^T  (pixel, n)
__device__ __align__(16) float g_h1[16 * 169 * 4096];   // layer1 pooled (c,13,13, n)
__device__ __align__(16) float g_h2[800 * 4096];        // layer2 pooled (feature, n)
__device__ __align__(16) float g_h3p[4][128 * 4096];    // fc1 split-K partial sums

// ---------------- f32x2 helpers (FFMA2 path: 2 MACs/instr) ----------------
static __device__ __forceinline__ unsigned long long ffma2(unsigned long long a,
                                                           unsigned long long b,
                                                           unsigned long long c) {
    unsigned long long d;
    asm("fma.rn.f32x2 %0, %1, %2, %3;" : "=l"(d) : "l"(a), "l"(b), "l"(c));
    return d;
}
static __device__ __forceinline__ unsigned long long pack2(float lo, float hi) {
    unsigned long long r;
    asm("mov.b64 %0, {%1, %2};" : "=l"(r) : "f"(lo), "f"(hi));
    return r;
}
static __device__ __forceinline__ float2 unpk(unsigned long long v) {
    float2 r;
    asm("mov.b64 {%0, %1}, %2;" : "=f"(r.x), "=f"(r.y) : "l"(v));
    return r;
}

// ---------------- K0: transpose x (4096,784) -> (784,4096) ----------------
__global__ __launch_bounds__(256) void k_transpose(const float* __restrict__ x) {
    __shared__ float tile[32][33];
    int p0 = blockIdx.x * 32;
    int n0 = blockIdx.y * 32;
    int tx = threadIdx.x, ty = threadIdx.y;   // (32,8)
#pragma unroll
    for (int i = 0; i < 4; i++) {
        int n = n0 + ty + i * 8, p = p0 + tx;
        float v = 0.f;
        if (p < 784) v = x[n * 784 + p];
        tile[ty + i * 8][tx] = v;
    }
    __syncthreads();
#pragma unroll
    for (int i = 0; i < 4; i++) {
        int p = p0 + ty + i * 8, n = n0 + tx;
        if (p < 784) g_xt[p * 4096 + n] = tile[tx][ty + i * 8];
    }
}

// ---------------- K1: layer1 lc-conv + relu + maxpool2 ----------------
// grid (169, 4), block 256. Each CTA: one pooled position, all 16 out channels,
// 1024 batch elems (4 per thread as 2x f32x2).
__global__ __launch_bounds__(256) void k_layer1(const float* __restrict__ w1,
                                                const float* __restrict__ b1) {
    int pos = blockIdx.x;                 // 0..168
    int pi = pos / 13, pj = pos % 13;
    int tid = threadIdx.x;
    __shared__ unsigned long long swd[16 * 36];   // [o][p][k], value duplicated
    __shared__ unsigned long long sbd[16 * 4];    // [o][p] bias duplicated

    for (int idx = tid; idx < 576; idx += 256) {
        int k = idx % 9, t = idx / 9;
        int p = t & 3, o = t >> 2;
        int ci = 2 * pi + (p >> 1), cj = 2 * pj + (p & 1);
        float w = w1[((o * 9 + k) * 26 + ci) * 26 + cj];
        swd[(o * 4 + p) * 9 + k] = pack2(w, w);
    }
    if (tid < 64) {
        int p = tid & 3, o = tid >> 2;
        int ci = 2 * pi + (p >> 1), cj = 2 * pj + (p & 1);
        float bb = b1[(o * 26 + ci) * 26 + cj];
        sbd[tid] = pack2(bb, bb);
    }
    __syncthreads();

    int n = (blockIdx.y * 256 + tid) * 4;

    unsigned long long xv[32];            // 4x4 region, 4 n-lanes (2 u64 each)
#pragma unroll
    for (int r = 0; r < 4; r++)
#pragma unroll
        for (int c = 0; c < 4; c++) {
            ulonglong2 v = *(const ulonglong2*)&g_xt[((2 * pi + r) * 28 + (2 * pj + c)) * 4096 + n];
            xv[(r * 4 + c) * 2 + 0] = v.x;
            xv[(r * 4 + c) * 2 + 1] = v.y;
        }

#pragma unroll 1
    for (int o = 0; o < 16; o++) {
        unsigned long long a[4][2];
#pragma unroll
        for (int p = 0; p < 4; p++) { a[p][0] = sbd[o * 4 + p]; a[p][1] = sbd[o * 4 + p]; }
#pragma unroll
        for (int p = 0; p < 4; p++) {
            int di = p >> 1, dj = p & 1;
#pragma unroll
            for (int k = 0; k < 9; k++) {
                unsigned long long w = swd[(o * 4 + p) * 9 + k];
                int xi = (di + k / 3) * 4 + (dj + k % 3);
                a[p][0] = ffma2(w, xv[xi * 2 + 0], a[p][0]);
                a[p][1] = ffma2(w, xv[xi * 2 + 1], a[p][1]);
            }
        }
        float2 a0 = unpk(a[0][0]), a1 = unpk(a[1][0]), a2 = unpk(a[2][0]), a3 = unpk(a[3][0]);
        float2 b0 = unpk(a[0][1]), bq = unpk(a[1][1]), b2_ = unpk(a[2][1]), b3 = unpk(a[3][1]);
        float4 r;
        r.x = fmaxf(fmaxf(fmaxf(a0.x, a1.x), fmaxf(a2.x, a3.x)), 0.f);
        r.y = fmaxf(fmaxf(fmaxf(a0.y, a1.y), fmaxf(a2.y, a3.y)), 0.f);
        r.z = fmaxf(fmaxf(fmaxf(b0.x, bq.x), fmaxf(b2_.x, b3.x)), 0.f);
        r.w = fmaxf(fmaxf(fmaxf(b0.y, bq.y), fmaxf(b2_.y, b3.y)), 0.f);
        *(float4*)&g_h1[(o * 169 + pos) * 4096 + n] = r;
    }
}

// ---------------- K2: layer2 lc-conv + relu + maxpool2 ----------------
// grid (25, 4, 8), block 256. CTA: one pooled position, 8 out channels,
// 512 batch elems (2 per thread = 1 f32x2).
// Weights fetched as p-paired LDS.128 (2 u64 per load) -> halves LDS issue.
__global__ __launch_bounds__(256) void k_layer2(const float* __restrict__ w2,
                                                const float* __restrict__ b2) {
    int pos = blockIdx.x;                 // 0..24
    int pi = pos / 5, pj = pos % 5;
    int o0 = blockIdx.y * 8;
    int tid = threadIdx.x;
    __shared__ __align__(16) unsigned long long swd[8 * 576];   // [((o*16+c)*9+k)*4+p]
    __shared__ unsigned long long sbd[8 * 4];

    for (int idx = tid; idx < 8 * 576; idx += 256) {
        int p = idx & 3;
        int t = idx >> 2;
        int k = t % 9;
        int u = t / 9;
        int c = u & 15, o = u >> 4;
        int ci = 2 * pi + (p >> 1), cj = 2 * pj + (p & 1);
        float w = w2[((((o0 + o) * 16 + c) * 9 + k) * 11 + ci) * 11 + cj];
        swd[idx] = pack2(w, w);
    }
    if (tid < 32) {
        int p = tid & 3, o = tid >> 2;
        int ci = 2 * pi + (p >> 1), cj = 2 * pj + (p & 1);
        float bb = b2[((o0 + o) * 11 + ci) * 11 + cj];
        sbd[tid] = pack2(bb, bb);
    }
    __syncthreads();

    int n = blockIdx.z * 512 + tid * 2;

    unsigned long long acc[8][4];
#pragma unroll
    for (int o = 0; o < 8; o++)
#pragma unroll
        for (int p = 0; p < 4; p++) acc[o][p] = sbd[o * 4 + p];

#pragma unroll 1
    for (int c = 0; c < 16; c++) {
        unsigned long long hv[16];
#pragma unroll
        for (int r = 0; r < 4; r++)
#pragma unroll
            for (int cc = 0; cc < 4; cc++)
                hv[r * 4 + cc] =
                    *(const unsigned long long*)&g_h1[((c * 169) + (2 * pi + r) * 13 + (2 * pj + cc)) * 4096 + n];
#pragma unroll
        for (int o = 0; o < 8; o++) {
#pragma unroll
            for (int k = 0; k < 9; k++) {
                int base = ((o * 16 + c) * 9 + k) * 4;
                ulonglong2 w01 = *(const ulonglong2*)&swd[base];      // p=0,1
                ulonglong2 w23 = *(const ulonglong2*)&swd[base + 2];  // p=2,3
                int kr = k / 3, kc = k % 3;
                acc[o][0] = ffma2(w01.x, hv[kr * 4 + kc],           acc[o][0]);
                acc[o][1] = ffma2(w01.y, hv[kr * 4 + kc + 1],       acc[o][1]);
                acc[o][2] = ffma2(w23.x, hv[(kr + 1) * 4 + kc],     acc[o][2]);
                acc[o][3] = ffma2(w23.y, hv[(kr + 1) * 4 + kc + 1], acc[o][3]);
            }
        }
    }

#pragma unroll
    for (int o = 0; o < 8; o++) {
        float2 a0 = unpk(acc[o][0]), a1 = unpk(acc[o][1]);
        float2 a2 = unpk(acc[o][2]), a3 = unpk(acc[o][3]);
        float2 r;
        r.x = fmaxf(fmaxf(fmaxf(a0.x, a1.x), fmaxf(a2.x, a3.x)), 0.f);
        r.y = fmaxf(fmaxf(fmaxf(a0.y, a1.y), fmaxf(a2.y, a3.y)), 0.f);
        *(float2*)&g_h2[((o0 + o) * 25 + pos) * 4096 + n] = r;
    }
}

// ---------------- K3: fc1 (800 -> 128), smem-staged h, split-K=4 ----------------
// grid (16 nb, 4 jt, 4 sk), block 256 = 32 nt x 8 jg. n-tile 256, j-tile 32,
// 200 ff per split in 8 chunks of 25. h staged in smem once per CTA chunk
// (kills the 8x cross-warp L1tex duplication); conflict-free LDS.128 reads.
// Thread tile: 8 n (two 4-n groups) x 4 j. Bias+ReLU deferred to k_fc2.
__global__ __launch_bounds__(256) void k_fc1(const float* __restrict__ w) {
    __shared__ __align__(16) float hs[25][256];              // 25.6 KB
    __shared__ __align__(16) unsigned long long wsd[25][32]; // 6.4 KB, dup
    int tid = threadIdx.x;
    int nt = tid & 31, jg = tid >> 5;
    int nbase = blockIdx.x * 256;
    int jb = blockIdx.y * 32;
    int f0 = blockIdx.z * 200;

    unsigned long long acc[4][4];
#pragma unroll
    for (int jj = 0; jj < 4; jj++)
#pragma unroll
        for (int q = 0; q < 4; q++) acc[jj][q] = 0ULL;

#pragma unroll 1
    for (int chunk = 0; chunk < 8; chunk++) {
        int fc = f0 + chunk * 25;
        __syncthreads();
        // stage h: 25 ff x 256 n, coalesced float4 (each line fetched once)
        for (int i = tid; i < 1600; i += 256) {
            int ff = i >> 6, q = i & 63;
            *(float4*)&hs[ff][q * 4] =
                *(const float4*)&g_h2[(fc + ff) * 4096 + nbase + q * 4];
        }
        // stage w (duplicated for f32x2)
        for (int i = tid; i < 800; i += 256) {
            int ff = i >> 5, jj = i & 31;
            float wv = w[(fc + ff) * 128 + jb + jj];
            wsd[ff][jj] = pack2(wv, wv);
        }
        __syncthreads();
#pragma unroll 5
        for (int ff = 0; ff < 25; ff++) {
            ulonglong2 ha = *(const ulonglong2*)&hs[ff][nt * 4];        // n group a
            ulonglong2 hb = *(const ulonglong2*)&hs[ff][128 + nt * 4];  // n group b
#pragma unroll
            for (int jj = 0; jj < 4; jj++) {
                unsigned long long wv = wsd[ff][jg * 4 + jj];
                acc[jj][0] = ffma2(wv, ha.x, acc[jj][0]);
                acc[jj][1] = ffma2(wv, ha.y, acc[jj][1]);
                acc[jj][2] = ffma2(wv, hb.x, acc[jj][2]);
                acc[jj][3] = ffma2(wv, hb.y, acc[jj][3]);
            }
        }
    }

#pragma unroll
    for (int jj = 0; jj < 4; jj++) {
        int j = jb + jg * 4 + jj;
        ulonglong2 va, vb;
        va.x = acc[jj][0]; va.y = acc[jj][1];
        vb.x = acc[jj][2]; vb.y = acc[jj][3];
        *(ulonglong2*)&g_h3p[blockIdx.z][j * 4096 + nbase + nt * 4]       = va;
        *(ulonglong2*)&g_h3p[blockIdx.z][j * 4096 + nbase + 128 + nt * 4] = vb;
    }
}

// ---------------- K4: fc2 (128 -> 10), with split-K reduce + bias + relu ----------------
__global__ __launch_bounds__(256) void k_fc2(const float* __restrict__ w,
                                             const float* __restrict__ b,
                                             const float* __restrict__ fc1b,
                                             float* __restrict__ out) {
    __shared__ float ws[1280];
    __shared__ float bs[10];
    __shared__ float b1s[128];
    int tid = threadIdx.x;
    for (int i = tid; i < 1280; i += 256) ws[i] = w[i];
    if (tid < 10) bs[tid] = b[tid];
    if (tid < 128) b1s[tid] = fc1b[tid];
    __syncthreads();

    int n = blockIdx.x * 256 + tid;
    float acc[10];
#pragma unroll
    for (int j = 0; j < 10; j++) acc[j] = bs[j];
#pragma unroll 4
    for (int f = 0; f < 128; f++) {
        float h = (g_h3p[0][f * 4096 + n] + g_h3p[1][f * 4096 + n]) +
                  (g_h3p[2][f * 4096 + n] + g_h3p[3][f * 4096 + n]);
        h = fmaxf(h + b1s[f], 0.f);
#pragma unroll
        for (int j = 0; j < 10; j++) acc[j] = fmaf(ws[f * 10 + j], h, acc[j]);
    }
#pragma unroll
    for (int j = 0; j < 10; j++) out[n * 10 + j] = acc[j];
}

// ---------------- launch ----------------
extern "C" void kernel_launch(void* const* d_in, const int* in_sizes, int n_in,
                              void* d_out, int out_size) {
    const float* x    = (const float*)d_in[0];
    const float* w1   = (const float*)d_in[1];
    const float* b1   = (const float*)d_in[2];
    const float* w2   = (const float*)d_in[3];
    const float* b2   = (const float*)d_in[4];
    const float* fc1w = (const float*)d_in[5];
    const float* fc1b = (const float*)d_in[6];
    const float* fc2w = (const float*)d_in[7];
    const float* fc2b = (const float*)d_in[8];
    float* out = (float*)d_out;

    k_transpose<<<dim3(25, 128), dim3(32, 8)>>>(x);
    k_layer1<<<dim3(169, 4), 256>>>(w1, b1);
    k_layer2<<<dim3(25, 4, 8), 256>>>(w2, b2);
    k_fc1<<<dim3(16, 4, 4), 256>>>(fc1w);
    k_fc2<<<16, 256>>>(fc2w, fc2b, fc1b, out);
}

// round 15
// speedup vs baseline: 1.3103x; 1.2453x over previous
#include <cuda_runtime.h>
#include <cuda_bf16.h>
#include <cstdint>

// ---------------- scratch (no mallocs allowed) ----------------
__device__ __align__(16) float g_xt[784 * 4096];        // x^T  (pixel, n)
__device__ __align__(16) float g_h1[16 * 169 * 4096];   // layer1 pooled (c,13,13, n)
__device__ __align__(16) float g_h2[800 * 4096];        // layer2 pooled (feature, n)
__device__ __align__(16) float g_h3p[8][128 * 4096];    // fc1 split-K partial sums
__device__ __align__(16) float g_h3[128 * 4096];        // fc1 reduced+relu

// ---------------- f32x2 helpers (FFMA2 path: 2 MACs/instr) ----------------
static __device__ __forceinline__ unsigned long long ffma2(unsigned long long a,
                                                           unsigned long long b,
                                                           unsigned long long c) {
    unsigned long long d;
    asm("fma.rn.f32x2 %0, %1, %2, %3;" : "=l"(d) : "l"(a), "l"(b), "l"(c));
    return d;
}
static __device__ __forceinline__ unsigned long long pack2(float lo, float hi) {
    unsigned long long r;
    asm("mov.b64 %0, {%1, %2};" : "=l"(r) : "f"(lo), "f"(hi));
    return r;
}
static __device__ __forceinline__ float2 unpk(unsigned long long v) {
    float2 r;
    asm("mov.b64 {%0, %1}, %2;" : "=f"(r.x), "=f"(r.y) : "l"(v));
    return r;
}

// ---------------- K0: transpose x (4096,784) -> (784,4096) ----------------
__global__ __launch_bounds__(256) void k_transpose(const float* __restrict__ x) {
    __shared__ float tile[32][33];
    int p0 = blockIdx.x * 32;
    int n0 = blockIdx.y * 32;
    int tx = threadIdx.x, ty = threadIdx.y;   // (32,8)
#pragma unroll
    for (int i = 0; i < 4; i++) {
        int n = n0 + ty + i * 8, p = p0 + tx;
        float v = 0.f;
        if (p < 784) v = x[n * 784 + p];
        tile[ty + i * 8][tx] = v;
    }
    __syncthreads();
#pragma unroll
    for (int i = 0; i < 4; i++) {
        int p = p0 + ty + i * 8, n = n0 + tx;
        if (p < 784) g_xt[p * 4096 + n] = tile[tx][ty + i * 8];
    }
}

// ---------------- K1: layer1 lc-conv + relu + maxpool2 ----------------
// grid (169, 4), block 256. Each CTA: one pooled position, all 16 out channels,
// 1024 batch elems (4 per thread as 2x f32x2).
__global__ __launch_bounds__(256) void k_layer1(const float* __restrict__ w1,
                                                const float* __restrict__ b1) {
    int pos = blockIdx.x;                 // 0..168
    int pi = pos / 13, pj = pos % 13;
    int tid = threadIdx.x;
    __shared__ unsigned long long swd[16 * 36];   // [o][p][k], value duplicated
    __shared__ unsigned long long sbd[16 * 4];    // [o][p] bias duplicated

    for (int idx = tid; idx < 576; idx += 256) {
        int k = idx % 9, t = idx / 9;
        int p = t & 3, o = t >> 2;
        int ci = 2 * pi + (p >> 1), cj = 2 * pj + (p & 1);
        float w = w1[((o * 9 + k) * 26 + ci) * 26 + cj];
        swd[(o * 4 + p) * 9 + k] = pack2(w, w);
    }
    if (tid < 64) {
        int p = tid & 3, o = tid >> 2;
        int ci = 2 * pi + (p >> 1), cj = 2 * pj + (p & 1);
        float bb = b1[(o * 26 + ci) * 26 + cj];
        sbd[tid] = pack2(bb, bb);
    }
    __syncthreads();

    int n = (blockIdx.y * 256 + tid) * 4;

    unsigned long long xv[32];            // 4x4 region, 4 n-lanes (2 u64 each)
#pragma unroll
    for (int r = 0; r < 4; r++)
#pragma unroll
        for (int c = 0; c < 4; c++) {
            ulonglong2 v = *(const ulonglong2*)&g_xt[((2 * pi + r) * 28 + (2 * pj + c)) * 4096 + n];
            xv[(r * 4 + c) * 2 + 0] = v.x;
            xv[(r * 4 + c) * 2 + 1] = v.y;
        }

#pragma unroll 1
    for (int o = 0; o < 16; o++) {
        unsigned long long a[4][2];
#pragma unroll
        for (int p = 0; p < 4; p++) { a[p][0] = sbd[o * 4 + p]; a[p][1] = sbd[o * 4 + p]; }
#pragma unroll
        for (int p = 0; p < 4; p++) {
            int di = p >> 1, dj = p & 1;
#pragma unroll
            for (int k = 0; k < 9; k++) {
                unsigned long long w = swd[(o * 4 + p) * 9 + k];
                int xi = (di + k / 3) * 4 + (dj + k % 3);
                a[p][0] = ffma2(w, xv[xi * 2 + 0], a[p][0]);
                a[p][1] = ffma2(w, xv[xi * 2 + 1], a[p][1]);
            }
        }
        float2 a0 = unpk(a[0][0]), a1 = unpk(a[1][0]), a2 = unpk(a[2][0]), a3 = unpk(a[3][0]);
        float2 b0 = unpk(a[0][1]), bq = unpk(a[1][1]), b2_ = unpk(a[2][1]), b3 = unpk(a[3][1]);
        float4 r;
        r.x = fmaxf(fmaxf(fmaxf(a0.x, a1.x), fmaxf(a2.x, a3.x)), 0.f);
        r.y = fmaxf(fmaxf(fmaxf(a0.y, a1.y), fmaxf(a2.y, a3.y)), 0.f);
        r.z = fmaxf(fmaxf(fmaxf(b0.x, bq.x), fmaxf(b2_.x, b3.x)), 0.f);
        r.w = fmaxf(fmaxf(fmaxf(b0.y, bq.y), fmaxf(b2_.y, b3.y)), 0.f);
        *(float4*)&g_h1[(o * 169 + pos) * 4096 + n] = r;
    }
}

// ---------------- K2: layer2 lc-conv + relu + maxpool2 (R9 version) ----------------
// grid (25, 4, 8), block 256. CTA: one pooled position, 8 out channels,
// 512 batch elems (2 per thread = 1 f32x2).
__global__ __launch_bounds__(256) void k_layer2(const float* __restrict__ w2,
                                                const float* __restrict__ b2) {
    int pos = blockIdx.x;                 // 0..24
    int pi = pos / 5, pj = pos % 5;
    int o0 = blockIdx.y * 8;
    int tid = threadIdx.x;
    __shared__ unsigned long long swd[8 * 576];   // [((o*16+c)*9+k)*4+p]
    __shared__ unsigned long long sbd[8 * 4];

    for (int idx = tid; idx < 8 * 576; idx += 256) {
        int p = idx & 3;
        int t = idx >> 2;
        int k = t % 9;
        int u = t / 9;
        int c = u & 15, o = u >> 4;
        int ci = 2 * pi + (p >> 1), cj = 2 * pj + (p & 1);
        float w = w2[((((o0 + o) * 16 + c) * 9 + k) * 11 + ci) * 11 + cj];
        swd[idx] = pack2(w, w);
    }
    if (tid < 32) {
        int p = tid & 3, o = tid >> 2;
        int ci = 2 * pi + (p >> 1), cj = 2 * pj + (p & 1);
        float bb = b2[((o0 + o) * 11 + ci) * 11 + cj];
        sbd[tid] = pack2(bb, bb);
    }
    __syncthreads();

    int n = blockIdx.z * 512 + tid * 2;

    unsigned long long acc[8][4];
#pragma unroll
    for (int o = 0; o < 8; o++)
#pragma unroll
        for (int p = 0; p < 4; p++) acc[o][p] = sbd[o * 4 + p];

#pragma unroll 1
    for (int c = 0; c < 16; c++) {
        unsigned long long hv[16];
#pragma unroll
        for (int r = 0; r < 4; r++)
#pragma unroll
            for (int cc = 0; cc < 4; cc++)
                hv[r * 4 + cc] =
                    *(const unsigned long long*)&g_h1[((c * 169) + (2 * pi + r) * 13 + (2 * pj + cc)) * 4096 + n];
#pragma unroll
        for (int o = 0; o < 8; o++) {
#pragma unroll
            for (int p = 0; p < 4; p++) {
                int di = p >> 1, dj = p & 1;
#pragma unroll
                for (int k = 0; k < 9; k++) {
                    acc[o][p] = ffma2(swd[((o * 16 + c) * 9 + k) * 4 + p],
                                      hv[(di + k / 3) * 4 + (dj + k % 3)], acc[o][p]);
                }
            }
        }
    }

#pragma unroll
    for (int o = 0; o < 8; o++) {
        float2 a0 = unpk(acc[o][0]), a1 = unpk(acc[o][1]);
        float2 a2 = unpk(acc[o][2]), a3 = unpk(acc[o][3]);
        float2 r;
        r.x = fmaxf(fmaxf(fmaxf(a0.x, a1.x), fmaxf(a2.x, a3.x)), 0.f);
        r.y = fmaxf(fmaxf(fmaxf(a0.y, a1.y), fmaxf(a2.y, a3.y)), 0.f);
        *(float2*)&g_h2[((o0 + o) * 25 + pos) * 4096 + n] = r;
    }
}

// ---------------- K3: fc1 (800 -> 128), smem-staged h, split-K=8 ----------------
// grid (16 nb, 4 jt, 8 sk) = 512 CTAs, block 256 = 32 nt x 8 jg. n-tile 256,
// j-tile 32, 100 ff per split in 4 chunks of 25. h staged in smem once per CTA
// chunk; conflict-free LDS.128. Thread tile: 8 n (two 4-n groups) x 4 j.
// Bias+ReLU deferred to k_reduce.
__global__ __launch_bounds__(256) void k_fc1(const float* __restrict__ w) {
    __shared__ __align__(16) float hs[25][256];              // 25.6 KB
    __shared__ __align__(16) unsigned long long wsd[25][32]; // 6.4 KB, dup
    int tid = threadIdx.x;
    int nt = tid & 31, jg = tid >> 5;
    int nbase = blockIdx.x * 256;
    int jb = blockIdx.y * 32;
    int f0 = blockIdx.z * 100;

    unsigned long long acc[4][4];
#pragma unroll
    for (int jj = 0; jj < 4; jj++)
#pragma unroll
        for (int q = 0; q < 4; q++) acc[jj][q] = 0ULL;

#pragma unroll 1
    for (int chunk = 0; chunk < 4; chunk++) {
        int fc = f0 + chunk * 25;
        __syncthreads();
        // stage h: 25 ff x 256 n, coalesced float4 (each line fetched once)
        for (int i = tid; i < 1600; i += 256) {
            int ff = i >> 6, q = i & 63;
            *(float4*)&hs[ff][q * 4] =
                *(const float4*)&g_h2[(fc + ff) * 4096 + nbase + q * 4];
        }
        // stage w (duplicated for f32x2)
        for (int i = tid; i < 800; i += 256) {
            int ff = i >> 5, jj = i & 31;
            float wv = w[(fc + ff) * 128 + jb + jj];
            wsd[ff][jj] = pack2(wv, wv);
        }
        __syncthreads();
#pragma unroll 5
        for (int ff = 0; ff < 25; ff++) {
            ulonglong2 ha = *(const ulonglong2*)&hs[ff][nt * 4];        // n group a
            ulonglong2 hb = *(const ulonglong2*)&hs[ff][128 + nt * 4];  // n group b
#pragma unroll
            for (int jj = 0; jj < 4; jj++) {
                unsigned long long wv = wsd[ff][jg * 4 + jj];
                acc[jj][0] = ffma2(wv, ha.x, acc[jj][0]);
                acc[jj][1] = ffma2(wv, ha.y, acc[jj][1]);
                acc[jj][2] = ffma2(wv, hb.x, acc[jj][2]);
                acc[jj][3] = ffma2(wv, hb.y, acc[jj][3]);
            }
        }
    }

#pragma unroll
    for (int jj = 0; jj < 4; jj++) {
        int j = jb + jg * 4 + jj;
        ulonglong2 va, vb;
        va.x = acc[jj][0]; va.y = acc[jj][1];
        vb.x = acc[jj][2]; vb.y = acc[jj][3];
        *(ulonglong2*)&g_h3p[blockIdx.z][j * 4096 + nbase + nt * 4]       = va;
        *(ulonglong2*)&g_h3p[blockIdx.z][j * 4096 + nbase + 128 + nt * 4] = vb;
    }
}

// ---------------- K3b: reduce 8 fc1 partials + bias + relu -> g_h3 ----------------
// grid 512, block 256. One float4 per thread; f = float4_idx >> 10.
__global__ __launch_bounds__(256) void k_reduce(const float* __restrict__ fc1b) {
    int e = blockIdx.x * 256 + threadIdx.x;     // float4 index, 0..131071
    int f = e >> 10;
    float bv = fc1b[f];
    float4 s0 = *(const float4*)&g_h3p[0][e * 4];
    float4 s1 = *(const float4*)&g_h3p[1][e * 4];
    float4 s2 = *(const float4*)&g_h3p[2][e * 4];
    float4 s3 = *(const float4*)&g_h3p[3][e * 4];
    float4 s4 = *(const float4*)&g_h3p[4][e * 4];
    float4 s5 = *(const float4*)&g_h3p[5][e * 4];
    float4 s6 = *(const float4*)&g_h3p[6][e * 4];
    float4 s7 = *(const float4*)&g_h3p[7][e * 4];
    float4 r;
    r.x = fmaxf(((s0.x + s1.x) + (s2.x + s3.x)) + ((s4.x + s5.x) + (s6.x + s7.x)) + bv, 0.f);
    r.y = fmaxf(((s0.y + s1.y) + (s2.y + s3.y)) + ((s4.y + s5.y) + (s6.y + s7.y)) + bv, 0.f);
    r.z = fmaxf(((s0.z + s1.z) + (s2.z + s3.z)) + ((s4.z + s5.z) + (s6.z + s7.z)) + bv, 0.f);
    r.w = fmaxf(((s0.w + s1.w) + (s2.w + s3.w)) + ((s4.w + s5.w) + (s6.w + s7.w)) + bv, 0.f);
    *(float4*)&g_h3[e * 4] = r;
}

// ---------------- K4: fc2 (128 -> 10) ----------------
// grid 64, block 256 = 4 f-groups x 64 n. Each thread 32 f; smem reduce.
__global__ __launch_bounds__(256) void k_fc2(const float* __restrict__ w,
                                             const float* __restrict__ b,
                                             float* __restrict__ out) {
    __shared__ float ws[1280];
    __shared__ float bs[10];
    __shared__ float red[256][10];
    int tid = threadIdx.x;
    for (int i = tid; i < 1280; i += 256) ws[i] = w[i];
    if (tid < 10) bs[tid] = b[tid];
    __syncthreads();

    int nl = tid & 63, fg = tid >> 6;
    int n = blockIdx.x * 64 + nl;
    float acc[10];
#pragma unroll
    for (int j = 0; j < 10; j++) acc[j] = 0.f;
#pragma unroll 8
    for (int ff = 0; ff < 32; ff++) {
        int f = fg * 32 + ff;
        float h = g_h3[f * 4096 + n];
#pragma unroll
        for (int j = 0; j < 10; j++) acc[j] = fmaf(ws[f * 10 + j], h, acc[j]);
    }
#pragma unroll
    for (int j = 0; j < 10; j++) red[tid][j] = acc[j];
    __syncthreads();
    if (fg == 0) {
#pragma unroll
        for (int j = 0; j < 10; j++) {
            float v = (red[nl][j] + red[nl + 64][j]) +
                      (red[nl + 128][j] + red[nl + 192][j]) + bs[j];
            out[n * 10 + j] = v;
        }
    }
}

// ---------------- launch ----------------
extern "C" void kernel_launch(void* const* d_in, const int* in_sizes, int n_in,
                              void* d_out, int out_size) {
    const float* x    = (const float*)d_in[0];
    const float* w1   = (const float*)d_in[1];
    const float* b1   = (const float*)d_in[2];
    const float* w2   = (const float*)d_in[3];
    const float* b2   = (const float*)d_in[4];
    const float* fc1w = (const float*)d_in[5];
    const float* fc1b = (const float*)d_in[6];
    const float* fc2w = (const float*)d_in[7];
    const float* fc2b = (const float*)d_in[8];
    float* out = (float*)d_out;

    k_transpose<<<dim3(25, 128), dim3(32, 8)>>>(x);
    k_layer1<<<dim3(169, 4), 256>>>(w1, b1);
    k_layer2<<<dim3(25, 4, 8), 256>>>(w2, b2);
    k_fc1<<<dim3(16, 4, 8), 256>>>(fc1w);
    k_reduce<<<512, 256>>>(fc1b);
    k_fc2<<<64, 256>>>(fc2w, fc2b, out);
}